// round 16
// baseline (speedup 1.0000x reference)
#include <cuda_runtime.h>
#include <cuda_fp16.h>
#include <cstdint>
#include <cstddef>

#define QK_SCALE 0.08838834764831843f   // 1/sqrt(128)

// TWO fp16 tile slots [64 rows][128 dims], row stride 136 halves = 272B
// (bank start advances 4 words/row -> conflict-free ldmatrix). K | V.
#define RSB  272
#define TSZ  (64 * RSB)          // 17408 B
#define S_K  0
#define S_V  TSZ
#define SMEM_BYTES (2 * TSZ)     // 34816 B -> 6 CTAs/SM

static __device__ __forceinline__ uint32_t smem_u32(const void* p){
    uint32_t a;
    asm("{ .reg .u64 t; cvta.to.shared.u64 t, %1; cvt.u32.u64 %0, t; }" : "=r"(a) : "l"(p));
    return a;
}
static __device__ __forceinline__ uint32_t h2(float a, float b){
    __half2 h = __floats2half2_rn(a, b);
    return *reinterpret_cast<uint32_t*>(&h);
}
static __device__ __forceinline__ void ldsm4(uint32_t* r, uint32_t addr){
    asm volatile("ldmatrix.sync.aligned.m8n8.x4.shared.b16 {%0,%1,%2,%3}, [%4];"
        : "=r"(r[0]), "=r"(r[1]), "=r"(r[2]), "=r"(r[3]) : "r"(addr));
}
static __device__ __forceinline__ void ldsm4t(uint32_t* r, uint32_t addr){
    asm volatile("ldmatrix.sync.aligned.m8n8.x4.trans.shared.b16 {%0,%1,%2,%3}, [%4];"
        : "=r"(r[0]), "=r"(r[1]), "=r"(r[2]), "=r"(r[3]) : "r"(addr));
}
static __device__ __forceinline__ void mma16816(float* c, const uint32_t* a, const uint32_t* b){
    asm volatile("mma.sync.aligned.m16n8k16.row.col.f32.f16.f16.f32 "
        "{%0,%1,%2,%3}, {%4,%5,%6,%7}, {%8,%9}, {%0,%1,%2,%3};"
        : "+f"(c[0]), "+f"(c[1]), "+f"(c[2]), "+f"(c[3])
        : "r"(a[0]), "r"(a[1]), "r"(a[2]), "r"(a[3]), "r"(b[0]), "r"(b[1]));
}
static __device__ __forceinline__ void stcs2(float* p, float a, float b){
    asm volatile("st.global.cs.v2.f32 [%0], {%1, %2};" :: "l"(p), "f"(a), "f"(b) : "memory");
}

__global__ __launch_bounds__(128, 6)
void attn_hmma(const float* __restrict__ qkv, const int* __restrict__ kvp,
               float* __restrict__ out)
{
    extern __shared__ char smem[];
    const uint32_t sb = smem_u32(smem);
    const int tid  = threadIdx.x;
    const int w    = tid >> 5;
    const int lane = tid & 31;
    const int h    = blockIdx.x & 31;
    const int b    = blockIdx.x >> 5;
    const int kvlen = kvp ? *kvp : 64;
    const int q = lane & 3;

    // ---- Q fragment pointers (loads issued in QK loop) ----
    const int r0 = w * 16;
    const int ra = r0 + (lane >> 2);            // frag rows ra, ra+8
    const float* qrowA = qkv + ((size_t)(b * 64 + ra) * 32 + h) * 384 + q * 2;
    const float* qrowB = qrowA + (size_t)8 * 32 * 384;   // row ra+8
    float2 x0 = *(const float2*)(qrowA + 0);
    float2 x1 = *(const float2*)(qrowB + 0);
    float2 x2 = *(const float2*)(qrowA + 8);
    float2 x3 = *(const float2*)(qrowB + 8);

    // ---- phase 1: K only -> fp16 smem tile ----
    const float4* srcbase = (const float4*)(qkv + ((size_t)(b * 64) * 32 + h) * 384);
    const size_t rstride = 32 * 96;              // one seq row in float4 units
    #pragma unroll 4
    for (int r = w; r < 64; r += 4) {
        float4 k4 = srcbase[(size_t)r * rstride / 96 * 96 / 96 * 96 + 0]; // placeholder avoided below
        (void)k4;
        break;
    }
    // (clean version of the K loop)
    #pragma unroll 4
    for (int r = w; r < 64; r += 4) {
        const float4* src = (const float4*)(qkv + ((size_t)(b * 64 + r) * 32 + h) * 384);
        float4 k4 = src[32 + lane];
        *(uint2*)(smem + S_K + r * RSB + lane * 8) = make_uint2(h2(k4.x, k4.y), h2(k4.z, k4.w));
    }

    // V pair-0 LDGs issued BEFORE the barrier (overlap barrier wait)
    const int rv0 = w;                           // V rows this warp: w + 4*i, i=0..15
    const float4* vsrc0 = (const float4*)(qkv + ((size_t)(b * 64 + rv0) * 32 + h) * 384) + 64 + lane;
    const size_t vrow4 = (size_t)4 * 32 * 96;    // 4 seq rows in float4 units
    float4 va = vsrc0[0];
    float4 vb = vsrc0[vrow4];

    __syncthreads();    // barrier 1: K tile ready

    // ---- QK^T with V software-pipelined through the loop ----
    float s[8][4];
    #pragma unroll
    for (int nt = 0; nt < 8; nt++)
        #pragma unroll
        for (int j = 0; j < 4; j++) s[nt][j] = 0.0f;

    // B-frag (K, non-trans): key (lane&7)+((lane&16)?8:0), dim half via lane bit3
    const uint32_t bK = sb + S_K + (uint32_t)((((lane & 7) + ((lane & 16) ? 8 : 0)) * RSB) + ((lane & 8) ? 16 : 0));

    #pragma unroll
    for (int kk = 0; kk < 8; kk++) {
        // store the V pair loaded one stage earlier; load the next pair
        const int rv = w + 8 * kk;               // rows rv, rv+4
        *(uint2*)(smem + S_V + rv * RSB + lane * 8)       = make_uint2(h2(va.x, va.y), h2(va.z, va.w));
        *(uint2*)(smem + S_V + (rv + 4) * RSB + lane * 8) = make_uint2(h2(vb.x, vb.y), h2(vb.z, vb.w));
        if (kk < 7) {
            va = vsrc0[(size_t)(2 * kk + 2) * vrow4];
            vb = vsrc0[(size_t)(2 * kk + 3) * vrow4];
        }

        uint32_t a[4];
        a[0] = h2(x0.x * QK_SCALE, x0.y * QK_SCALE);
        a[1] = h2(x1.x * QK_SCALE, x1.y * QK_SCALE);
        a[2] = h2(x2.x * QK_SCALE, x2.y * QK_SCALE);
        a[3] = h2(x3.x * QK_SCALE, x3.y * QK_SCALE);
        if (kk < 7) {
            const int d = (kk + 1) * 16;
            x0 = *(const float2*)(qrowA + d);
            x1 = *(const float2*)(qrowB + d);
            x2 = *(const float2*)(qrowA + d + 8);
            x3 = *(const float2*)(qrowB + d + 8);
        }
        #pragma unroll
        for (int nt2 = 0; nt2 < 4; nt2++) {
            uint32_t bb[4];
            ldsm4(bb, bK + nt2 * (16 * RSB) + kk * 32);
            mma16816(s[2*nt2],   a, bb);
            mma16816(s[2*nt2+1], a, bb + 2);
        }
    }

    // ---- softmax in C-fragment layout (rows lane/4 and lane/4+8) ----
    float mlo = -3.0e38f, mhi = -3.0e38f;
    #pragma unroll
    for (int nt = 0; nt < 8; nt++) {
        #pragma unroll
        for (int j = 0; j < 4; j++) {
            int col = nt * 8 + q * 2 + (j & 1);
            if (col >= kvlen) s[nt][j] = -3.0e38f;
        }
        mlo = fmaxf(mlo, fmaxf(s[nt][0], s[nt][1]));
        mhi = fmaxf(mhi, fmaxf(s[nt][2], s[nt][3]));
    }
    mlo = fmaxf(mlo, __shfl_xor_sync(0xffffffffu, mlo, 1));
    mlo = fmaxf(mlo, __shfl_xor_sync(0xffffffffu, mlo, 2));
    mhi = fmaxf(mhi, __shfl_xor_sync(0xffffffffu, mhi, 1));
    mhi = fmaxf(mhi, __shfl_xor_sync(0xffffffffu, mhi, 2));

    float slo = 0.0f, shi = 0.0f;
    #pragma unroll
    for (int nt = 0; nt < 8; nt++) {
        s[nt][0] = __expf(s[nt][0] - mlo);
        s[nt][1] = __expf(s[nt][1] - mlo);
        s[nt][2] = __expf(s[nt][2] - mhi);
        s[nt][3] = __expf(s[nt][3] - mhi);
        slo += s[nt][0] + s[nt][1];
        shi += s[nt][2] + s[nt][3];
    }
    slo += __shfl_xor_sync(0xffffffffu, slo, 1);
    slo += __shfl_xor_sync(0xffffffffu, slo, 2);
    shi += __shfl_xor_sync(0xffffffffu, shi, 1);
    shi += __shfl_xor_sync(0xffffffffu, shi, 2);
    const float invlo = 1.0f / slo;
    const float invhi = 1.0f / shi;

    // ---- P (unnormalized) -> fp16 A-fragments (C layout == A layout) ----
    uint32_t p[4][4];
    #pragma unroll
    for (int kt = 0; kt < 4; kt++) {
        p[kt][0] = h2(s[2*kt][0],   s[2*kt][1]);
        p[kt][1] = h2(s[2*kt][2],   s[2*kt][3]);
        p[kt][2] = h2(s[2*kt+1][0], s[2*kt+1][1]);
        p[kt][3] = h2(s[2*kt+1][2], s[2*kt+1][3]);
    }

    __syncthreads();    // barrier 2: all V stores visible before PV reads

    // ---- O = P @ V in two 64-dim halves ----
    // B-frag (V, trans): key (lane&7)+((lane&8)?8:0), 8-dim half via lane bit4
    const uint32_t bV = sb + S_V + (uint32_t)((((lane & 7) + ((lane & 8) ? 8 : 0)) * RSB) + ((lane & 16) ? 16 : 0));
    float* o0 = out + ((size_t)(b * 64 + ra) * 32 + h) * 128 + q * 2;
    float* o1 = out + ((size_t)(b * 64 + ra + 8) * 32 + h) * 128 + q * 2;

    #pragma unroll
    for (int hd = 0; hd < 2; hd++) {
        float o[8][4];
        #pragma unroll
        for (int nt = 0; nt < 8; nt++)
            #pragma unroll
            for (int j = 0; j < 4; j++) o[nt][j] = 0.0f;

        #pragma unroll
        for (int kt = 0; kt < 4; kt++) {
            #pragma unroll
            for (int nt2 = 0; nt2 < 4; nt2++) {
                uint32_t bb[4];
                ldsm4t(bb, bV + (uint32_t)(kt * (16 * RSB) + hd * 128 + nt2 * 32));
                mma16816(o[2*nt2],   p[kt], bb);
                mma16816(o[2*nt2+1], p[kt], bb + 2);
            }
        }
        #pragma unroll
        for (int nt = 0; nt < 8; nt++) {
            stcs2(o0 + hd * 64 + nt * 8, o[nt][0] * invlo, o[nt][1] * invlo);
            stcs2(o1 + hd * 64 + nt * 8, o[nt][2] * invhi, o[nt][3] * invhi);
        }
    }
}

extern "C" void kernel_launch(void* const* d_in, const int* in_sizes, int n_in,
                              void* d_out, int out_size)
{
    const float* qkv  = (const float*)d_in[0];
    const int*   kvlp = (n_in > 1) ? (const int*)d_in[1] : nullptr;
    float*       out  = (float*)d_out;

    cudaFuncSetAttribute(attn_hmma, cudaFuncAttributeMaxDynamicSharedMemorySize, SMEM_BYTES);
    attn_hmma<<<128 * 32, 128, SMEM_BYTES>>>(qkv, kvlp, out);
}

// round 17
// speedup vs baseline: 1.0913x; 1.0913x over previous
#include <cuda_runtime.h>
#include <cuda_fp16.h>
#include <cstdint>
#include <cstddef>

#define QK_SCALE 0.08838834764831843f   // 1/sqrt(128)

// TWO fp16 tile slots [64 rows][128 dims], row stride 136 halves = 272B
// (bank start advances 4 words/row -> conflict-free ldmatrix). K | V.
#define RSB  272
#define TSZ  (64 * RSB)          // 17408 B
#define S_K  0
#define S_V  TSZ
#define SMEM_BYTES (2 * TSZ)     // 34816 B -> 6 CTAs/SM

static __device__ __forceinline__ uint32_t smem_u32(const void* p){
    uint32_t a;
    asm("{ .reg .u64 t; cvta.to.shared.u64 t, %1; cvt.u32.u64 %0, t; }" : "=r"(a) : "l"(p));
    return a;
}
static __device__ __forceinline__ uint32_t h2(float a, float b){
    __half2 h = __floats2half2_rn(a, b);
    return *reinterpret_cast<uint32_t*>(&h);
}
static __device__ __forceinline__ void ldsm4(uint32_t* r, uint32_t addr){
    asm volatile("ldmatrix.sync.aligned.m8n8.x4.shared.b16 {%0,%1,%2,%3}, [%4];"
        : "=r"(r[0]), "=r"(r[1]), "=r"(r[2]), "=r"(r[3]) : "r"(addr));
}
static __device__ __forceinline__ void ldsm4t(uint32_t* r, uint32_t addr){
    asm volatile("ldmatrix.sync.aligned.m8n8.x4.trans.shared.b16 {%0,%1,%2,%3}, [%4];"
        : "=r"(r[0]), "=r"(r[1]), "=r"(r[2]), "=r"(r[3]) : "r"(addr));
}
static __device__ __forceinline__ void mma16816(float* c, const uint32_t* a, const uint32_t* b){
    asm volatile("mma.sync.aligned.m16n8k16.row.col.f32.f16.f16.f32 "
        "{%0,%1,%2,%3}, {%4,%5,%6,%7}, {%8,%9}, {%0,%1,%2,%3};"
        : "+f"(c[0]), "+f"(c[1]), "+f"(c[2]), "+f"(c[3])
        : "r"(a[0]), "r"(a[1]), "r"(a[2]), "r"(a[3]), "r"(b[0]), "r"(b[1]));
}
static __device__ __forceinline__ void stcs2(float* p, float a, float b){
    asm volatile("st.global.cs.v2.f32 [%0], {%1, %2};" :: "l"(p), "f"(a), "f"(b) : "memory");
}
static __device__ __forceinline__ void pref_l2(const void* p){
    asm volatile("prefetch.global.L2 [%0];" :: "l"(p));
}

__global__ __launch_bounds__(128, 6)
void attn_hmma(const float* __restrict__ qkv, const int* __restrict__ kvp,
               float* __restrict__ out)
{
    extern __shared__ char smem[];
    const uint32_t sb = smem_u32(smem);
    const int tid  = threadIdx.x;
    const int w    = tid >> 5;
    const int lane = tid & 31;
    const int h    = blockIdx.x & 31;
    const int b    = blockIdx.x >> 5;
    const int kvlen = kvp ? *kvp : 64;
    const int q = lane & 3;

    // ---- Q fragment pointers; first Q loads issued up front ----
    const int r0 = w * 16;
    const int ra = r0 + (lane >> 2);            // frag rows ra, ra+8
    const float* qrowA = qkv + ((size_t)(b * 64 + ra) * 32 + h) * 384 + q * 2;
    const float* qrowB = qrowA + (size_t)8 * 32 * 384;   // row ra+8
    float2 x0 = *(const float2*)(qrowA + 0);
    float2 x1 = *(const float2*)(qrowB + 0);
    float2 x2 = *(const float2*)(qrowA + 8);
    float2 x3 = *(const float2*)(qrowB + 8);

    // ---- phase 1: K -> fp16 smem tile ----
    #pragma unroll 4
    for (int r = w; r < 64; r += 4) {
        const float4* src = (const float4*)(qkv + ((size_t)(b * 64 + r) * 32 + h) * 384);
        float4 k4 = src[32 + lane];     // K dims 4*lane..+3
        *(uint2*)(smem + S_K + r * RSB + lane * 8) = make_uint2(h2(k4.x, k4.y), h2(k4.z, k4.w));
    }
    __syncthreads();    // barrier 1: K tile ready

    // ---- L2 prefetch of this warp's V rows (reg-free; covered by QK+softmax) ----
    const float4* vsrc0 = (const float4*)(qkv + ((size_t)(b * 64 + w) * 32 + h) * 384) + 64 + lane;
    const size_t vrow4 = (size_t)4 * 32 * 96;   // 4 seq rows in float4 units
    #pragma unroll
    for (int i = 0; i < 16; i++) pref_l2(vsrc0 + (size_t)i * vrow4);

    // ---- QK^T: warp owns rows [16w,16w+16) x 64 keys, single fp16 pass ----
    float s[8][4];
    #pragma unroll
    for (int nt = 0; nt < 8; nt++)
        #pragma unroll
        for (int j = 0; j < 4; j++) s[nt][j] = 0.0f;

    // B-frag (K, non-trans): key (lane&7)+((lane&16)?8:0), dim half via lane bit3
    const uint32_t bK = sb + S_K + (uint32_t)((((lane & 7) + ((lane & 16) ? 8 : 0)) * RSB) + ((lane & 8) ? 16 : 0));

    #pragma unroll
    for (int kk = 0; kk < 8; kk++) {
        uint32_t a[4];
        a[0] = h2(x0.x * QK_SCALE, x0.y * QK_SCALE);
        a[1] = h2(x1.x * QK_SCALE, x1.y * QK_SCALE);
        a[2] = h2(x2.x * QK_SCALE, x2.y * QK_SCALE);
        a[3] = h2(x3.x * QK_SCALE, x3.y * QK_SCALE);
        if (kk < 7) {
            const int d = (kk + 1) * 16;
            x0 = *(const float2*)(qrowA + d);
            x1 = *(const float2*)(qrowB + d);
            x2 = *(const float2*)(qrowA + d + 8);
            x3 = *(const float2*)(qrowB + d + 8);
        }
        #pragma unroll
        for (int nt2 = 0; nt2 < 4; nt2++) {
            uint32_t bb[4];
            ldsm4(bb, bK + nt2 * (16 * RSB) + kk * 32);
            mma16816(s[2*nt2],   a, bb);
            mma16816(s[2*nt2+1], a, bb + 2);
        }
    }

    // ---- softmax in C-fragment layout (rows lane/4 and lane/4+8) ----
    float mlo = -3.0e38f, mhi = -3.0e38f;
    #pragma unroll
    for (int nt = 0; nt < 8; nt++) {
        #pragma unroll
        for (int j = 0; j < 4; j++) {
            int col = nt * 8 + q * 2 + (j & 1);
            if (col >= kvlen) s[nt][j] = -3.0e38f;
        }
        mlo = fmaxf(mlo, fmaxf(s[nt][0], s[nt][1]));
        mhi = fmaxf(mhi, fmaxf(s[nt][2], s[nt][3]));
    }
    mlo = fmaxf(mlo, __shfl_xor_sync(0xffffffffu, mlo, 1));
    mlo = fmaxf(mlo, __shfl_xor_sync(0xffffffffu, mlo, 2));
    mhi = fmaxf(mhi, __shfl_xor_sync(0xffffffffu, mhi, 1));
    mhi = fmaxf(mhi, __shfl_xor_sync(0xffffffffu, mhi, 2));

    float slo = 0.0f, shi = 0.0f;
    #pragma unroll
    for (int nt = 0; nt < 8; nt++) {
        s[nt][0] = __expf(s[nt][0] - mlo);
        s[nt][1] = __expf(s[nt][1] - mlo);
        s[nt][2] = __expf(s[nt][2] - mhi);
        s[nt][3] = __expf(s[nt][3] - mhi);
        slo += s[nt][0] + s[nt][1];
        shi += s[nt][2] + s[nt][3];
    }
    slo += __shfl_xor_sync(0xffffffffu, slo, 1);
    slo += __shfl_xor_sync(0xffffffffu, slo, 2);
    shi += __shfl_xor_sync(0xffffffffu, shi, 1);
    shi += __shfl_xor_sync(0xffffffffu, shi, 2);
    const float invlo = 1.0f / slo;
    const float invhi = 1.0f / shi;

    // ---- P (unnormalized) -> fp16 A-fragments (C layout == A layout) ----
    uint32_t p[4][4];
    #pragma unroll
    for (int kt = 0; kt < 4; kt++) {
        p[kt][0] = h2(s[2*kt][0],   s[2*kt][1]);
        p[kt][1] = h2(s[2*kt][2],   s[2*kt][3]);
        p[kt][2] = h2(s[2*kt+1][0], s[2*kt+1][1]);
        p[kt][3] = h2(s[2*kt+1][2], s[2*kt+1][3]);
    }

    // ---- phase 2: V (L2-hot) -> fp16 smem tile, fully unrolled (MLP=16) ----
    #pragma unroll
    for (int i = 0; i < 16; i++) {
        float4 v4 = vsrc0[(size_t)i * vrow4];
        *(uint2*)(smem + S_V + (w + 4 * i) * RSB + lane * 8) = make_uint2(h2(v4.x, v4.y), h2(v4.z, v4.w));
    }
    __syncthreads();    // barrier 2: V tile ready

    // ---- O = P @ V in two 64-dim halves ----
    // B-frag (V, trans): key (lane&7)+((lane&8)?8:0), 8-dim half via lane bit4
    const uint32_t bV = sb + S_V + (uint32_t)((((lane & 7) + ((lane & 8) ? 8 : 0)) * RSB) + ((lane & 16) ? 16 : 0));
    float* o0 = out + ((size_t)(b * 64 + ra) * 32 + h) * 128 + q * 2;
    float* o1 = out + ((size_t)(b * 64 + ra + 8) * 32 + h) * 128 + q * 2;

    #pragma unroll
    for (int hd = 0; hd < 2; hd++) {
        float o[8][4];
        #pragma unroll
        for (int nt = 0; nt < 8; nt++)
            #pragma unroll
            for (int j = 0; j < 4; j++) o[nt][j] = 0.0f;

        #pragma unroll
        for (int kt = 0; kt < 4; kt++) {
            #pragma unroll
            for (int nt2 = 0; nt2 < 4; nt2++) {
                uint32_t bb[4];
                ldsm4t(bb, bV + (uint32_t)(kt * (16 * RSB) + hd * 128 + nt2 * 32));
                mma16816(o[2*nt2],   p[kt], bb);
                mma16816(o[2*nt2+1], p[kt], bb + 2);
            }
        }
        #pragma unroll
        for (int nt = 0; nt < 8; nt++) {
            stcs2(o0 + hd * 64 + nt * 8, o[nt][0] * invlo, o[nt][1] * invlo);
            stcs2(o1 + hd * 64 + nt * 8, o[nt][2] * invhi, o[nt][3] * invhi);
        }
    }
}

extern "C" void kernel_launch(void* const* d_in, const int* in_sizes, int n_in,
                              void* d_out, int out_size)
{
    const float* qkv  = (const float*)d_in[0];
    const int*   kvlp = (n_in > 1) ? (const int*)d_in[1] : nullptr;
    float*       out  = (float*)d_out;

    cudaFuncSetAttribute(attn_hmma, cudaFuncAttributeMaxDynamicSharedMemorySize, SMEM_BYTES);
    attn_hmma<<<128 * 32, 128, SMEM_BYTES>>>(qkv, kvlp, out);
}